// round 1
// baseline (speedup 1.0000x reference)
#include <cuda_runtime.h>
#include <cstdint>

// ---------------------------------------------------------------------------
// Problem constants
// ---------------------------------------------------------------------------
#define VOCAB     10000
#define EMB       128
#define NDEM      2
#define B_ROWS    16384
#define SRC_COLS  (VOCAB + NDEM)     // 10002
#define NH        16                 // hidden width
#define NP        18                 // padded accumulator width: 16 + count + pad
#define KPAD      10240              // VOCAB padded to multiple of 128
#define KSPLIT    16
#define KRANGE    (KPAD / KSPLIT)    // 640
#define KT        128
#define NTILES    (KRANGE / KT)      // 5
#define TM        512                // rows per CTA tile
#define MTILES    (B_ROWS / TM)      // 32
#define THREADS   256

// Scratch (allocation-free rule: __device__ globals)
__device__ float g_EW1[KPAD * NP];                 // 10240 x 18 fp32  (~737 KB)
__device__ float g_S[KSPLIT * NP * B_ROWS];        // 16 x 18 x 16384 fp32 (~18.9 MB)

// ---------------------------------------------------------------------------
// f32x2 packed helpers (sm_100a packed-fp32 path; 2x FMA throughput)
// ---------------------------------------------------------------------------
__device__ __forceinline__ void fma_f32x2(unsigned long long& d,
                                          unsigned long long a,
                                          unsigned long long b) {
    asm("fma.rn.f32x2 %0, %1, %2, %0;" : "+l"(d) : "l"(a), "l"(b));
}
__device__ __forceinline__ unsigned long long pack2(float lo, float hi) {
    unsigned long long r;
    asm("mov.b64 %0, {%1, %2};" : "=l"(r) : "r"(__float_as_uint(lo)), "r"(__float_as_uint(hi)));
    return r;
}
__device__ __forceinline__ void unpack2(unsigned long long v, float& lo, float& hi) {
    unsigned a, b;
    asm("mov.b64 {%0, %1}, %2;" : "=r"(a), "=r"(b) : "l"(v));
    lo = __uint_as_float(a);
    hi = __uint_as_float(b);
}

// ---------------------------------------------------------------------------
// Kernel 0: EW1[k, n] = sum_d embed[k, d] * W1[2 + d, n]   (+ ones column, zero pad)
// ---------------------------------------------------------------------------
__global__ void ew1_kernel(const float* __restrict__ embed, const float* __restrict__ W1) {
    int t = blockIdx.x * blockDim.x + threadIdx.x;
    if (t >= KPAD * NP) return;
    int k = t / NP;
    int n = t - k * NP;
    float v = 0.f;
    if (k < VOCAB) {
        if (n < NH) {
            const float* er = embed + k * EMB;
            float a0 = 0.f, a1 = 0.f, a2 = 0.f, a3 = 0.f;
            #pragma unroll 8
            for (int d = 0; d < EMB; d += 4) {
                a0 += er[d + 0] * W1[(NDEM + d + 0) * NH + n];
                a1 += er[d + 1] * W1[(NDEM + d + 1) * NH + n];
                a2 += er[d + 2] * W1[(NDEM + d + 2) * NH + n];
                a3 += er[d + 3] * W1[(NDEM + d + 3) * NH + n];
            }
            v = (a0 + a1) + (a2 + a3);
        } else if (n == NH) {
            v = 1.f;   // ones column -> counts
        }
    }
    g_EW1[t] = v;
}

// ---------------------------------------------------------------------------
// Kernel 1: partial S[part] = mask_tile @ EW1_aug
//   grid = MTILES * KSPLIT CTAs, 256 threads each, 2 rows per thread.
//   Per K-tile: stage EW1 tile + src->bitmask (ballot) in smem, then
//   f32x2 FMA accumulation with broadcast LDS of the EW1 row.
// ---------------------------------------------------------------------------
__global__ __launch_bounds__(THREADS) void pool_kernel(const float* __restrict__ src) {
    __shared__ __align__(16) float sh_e[KT * NP];          // 9216 B
    __shared__ unsigned sh_bits[TM][KT / 32];              // 8192 B

    const int tid  = threadIdx.x;
    const int wid  = tid >> 5;
    const int lane = tid & 31;
    const int mtile = blockIdx.x >> 4;                     // / KSPLIT
    const int part  = blockIdx.x & (KSPLIT - 1);
    const int row0  = mtile * TM;
    const int kbase = part * KRANGE;
    const int r_loc = tid * 2;

    unsigned long long acc[2][9];
    #pragma unroll
    for (int r = 0; r < 2; ++r)
        #pragma unroll
        for (int j = 0; j < 9; ++j) acc[r][j] = 0ull;

    for (int t = 0; t < NTILES; ++t) {
        const int k0 = kbase + t * KT;

        // --- stage EW1 tile (KT x NP = 2304 floats, 9 per thread) ---
        #pragma unroll
        for (int i = 0; i < 9; ++i) {
            int idx = tid + i * THREADS;
            sh_e[idx] = g_EW1[k0 * NP + idx];
        }

        // --- stage src -> bitmask; coalesced lane-consecutive loads + ballot ---
        for (int c = wid; c < TM * (KT / 32); c += (THREADS / 32)) {
            int row = c >> 2;
            int cc  = c & 3;
            int kg  = k0 + cc * 32 + lane;
            float v = 0.f;
            if (kg < VOCAB)
                v = src[(long long)(row0 + row) * SRC_COLS + NDEM + kg];
            unsigned bal = __ballot_sync(0xffffffffu, v != 0.f);
            if (lane == 0) sh_bits[row][cc] = bal;
        }
        __syncthreads();

        unsigned bw0[4], bw1[4];
        #pragma unroll
        for (int w = 0; w < 4; ++w) {
            bw0[w] = sh_bits[r_loc][w];
            bw1[w] = sh_bits[r_loc + 1][w];
        }

        #pragma unroll
        for (int w = 0; w < 4; ++w) {
            const unsigned b0 = bw0[w], b1 = bw1[w];
            #pragma unroll 8
            for (int bit = 0; bit < 32; ++bit) {
                const float* ep = sh_e + (w * 32 + bit) * NP;
                unsigned long long e[9];
                #pragma unroll
                for (int j = 0; j < 9; ++j)
                    e[j] = *reinterpret_cast<const unsigned long long*>(ep + 2 * j);
                float m0 = ((b0 >> bit) & 1u) ? 1.f : 0.f;
                float m1 = ((b1 >> bit) & 1u) ? 1.f : 0.f;
                unsigned long long m0p = pack2(m0, m0);
                unsigned long long m1p = pack2(m1, m1);
                #pragma unroll
                for (int j = 0; j < 9; ++j) {
                    fma_f32x2(acc[0][j], e[j], m0p);
                    fma_f32x2(acc[1][j], e[j], m1p);
                }
            }
        }
        __syncthreads();
    }

    // --- write partials column-major for coalesced reduction later ---
    #pragma unroll
    for (int r = 0; r < 2; ++r) {
        int rg = row0 + r_loc + r;
        #pragma unroll
        for (int j = 0; j < 9; ++j) {
            float lo, hi;
            unpack2(acc[r][j], lo, hi);
            g_S[(part * NP + 2 * j + 0) * B_ROWS + rg] = lo;
            g_S[(part * NP + 2 * j + 1) * B_ROWS + rg] = hi;
        }
    }
}

// ---------------------------------------------------------------------------
// Kernel 2: reduce K-split partials + MLP epilogue
//   h = tanh(dem@W1[:2] + S/count + b1);  out = h@W2 + b2
// ---------------------------------------------------------------------------
__global__ void mlp_kernel(const float* __restrict__ src, const float* __restrict__ W1,
                           const float* __restrict__ b1, const float* __restrict__ W2,
                           const float* __restrict__ b2, float* __restrict__ out) {
    int r = blockIdx.x * blockDim.x + threadIdx.x;
    if (r >= B_ROWS) return;

    float s[17];
    #pragma unroll
    for (int n = 0; n < 17; ++n) s[n] = 0.f;
    #pragma unroll
    for (int p = 0; p < KSPLIT; ++p)
        #pragma unroll
        for (int n = 0; n < 17; ++n)
            s[n] += g_S[(p * NP + n) * B_ROWS + r];

    float inv = 1.f / s[16];
    float d0 = src[(long long)r * SRC_COLS + 0];
    float d1 = src[(long long)r * SRC_COLS + 1];

    float o0 = b2[0], o1 = b2[1];
    #pragma unroll
    for (int j = 0; j < NH; ++j) {
        float z = d0 * W1[j] + d1 * W1[NH + j] + s[j] * inv + b1[j];
        float h = tanhf(z);
        o0 += h * W2[2 * j + 0];
        o1 += h * W2[2 * j + 1];
    }
    out[2 * r + 0] = o0;
    out[2 * r + 1] = o1;
}

// ---------------------------------------------------------------------------
// Launch
// ---------------------------------------------------------------------------
extern "C" void kernel_launch(void* const* d_in, const int* in_sizes, int n_in,
                              void* d_out, int out_size) {
    // Map inputs by element count (defensive against metadata ordering)
    int iSrc = 0, iEmb = 1, iW1 = 2, iB1 = 3, iW2 = 4, iB2 = 5;
    for (int i = 0; i < n_in; ++i) {
        int s = in_sizes[i];
        if      (s == B_ROWS * SRC_COLS)   iSrc = i;
        else if (s == VOCAB * EMB)         iEmb = i;
        else if (s == (NDEM + EMB) * NH)   iW1  = i;
        else if (s == NH)                  iB1  = i;
        else if (s == NH * 2)              iW2  = i;
        else if (s == 2)                   iB2  = i;
    }
    const float* src   = (const float*)d_in[iSrc];
    const float* embed = (const float*)d_in[iEmb];
    const float* W1    = (const float*)d_in[iW1];
    const float* b1    = (const float*)d_in[iB1];
    const float* W2    = (const float*)d_in[iW2];
    const float* b2    = (const float*)d_in[iB2];
    float* out = (float*)d_out;

    ew1_kernel<<<(KPAD * NP + 255) / 256, 256>>>(embed, W1);
    pool_kernel<<<MTILES * KSPLIT, THREADS>>>(src);
    mlp_kernel<<<(B_ROWS + 255) / 256, 256>>>(src, W1, b1, W2, b2, out);
}

// round 2
// speedup vs baseline: 2.0757x; 2.0757x over previous
#include <cuda_runtime.h>
#include <cstdint>

// ---------------------------------------------------------------------------
// Problem constants
// ---------------------------------------------------------------------------
#define VOCAB     10000
#define EMB       128
#define NDEM      2
#define B_ROWS    16384
#define SRC_COLS  (VOCAB + NDEM)     // 10002
#define NH        16                 // hidden width
#define NP        18                 // accumulator width: 16 + count + pad
#define KPAD      10240              // VOCAB padded to multiple of 128
#define KSPLIT    16
#define KRANGE    (KPAD / KSPLIT)    // 640
#define KT        128
#define NTILES    (KRANGE / KT)      // 5
#define TM        512                // rows per CTA tile
#define MTILES    (B_ROWS / TM)      // 32
#define THREADS   256

// Scratch (allocation-free rule: __device__ globals)
__device__ float g_EW1[KPAD * NP];                 // 10240 x 18 fp32
__device__ float g_S[KSPLIT * NP * B_ROWS];        // 16 x 18 x 16384 fp32

// ---------------------------------------------------------------------------
// f32x2 packed helpers (2x FMA-pipe throughput)
// ---------------------------------------------------------------------------
__device__ __forceinline__ void fma_f32x2(unsigned long long& d,
                                          unsigned long long a,
                                          unsigned long long b) {
    asm("fma.rn.f32x2 %0, %1, %2, %0;" : "+l"(d) : "l"(a), "l"(b));
}
__device__ __forceinline__ unsigned long long pack2(float lo, float hi) {
    unsigned long long r;
    asm("mov.b64 %0, {%1, %2};" : "=l"(r) : "r"(__float_as_uint(lo)), "r"(__float_as_uint(hi)));
    return r;
}
__device__ __forceinline__ void unpack2(unsigned long long v, float& lo, float& hi) {
    unsigned a, b;
    asm("mov.b64 {%0, %1}, %2;" : "=r"(a), "=r"(b) : "l"(v));
    lo = __uint_as_float(a);
    hi = __uint_as_float(b);
}

// ---------------------------------------------------------------------------
// Kernel 0: EW1[k, n] = sum_d embed[k, d] * W1[2 + d, n]  (+ ones col, pad)
//   Block = 288 threads = 16 k-rows x 18 n.  embed rows + W1 staged in smem.
// ---------------------------------------------------------------------------
__global__ __launch_bounds__(288) void ew1_kernel(const float* __restrict__ embed,
                                                  const float* __restrict__ W1) {
    __shared__ float sh_emb[16][EMB];     // 8 KB
    __shared__ float sh_w1[EMB][NH];      // 8 KB

    const int tid = threadIdx.x;
    const int k0  = blockIdx.x * 16;

    // stage W1[2:130, :16]  (2048 floats)
    for (int i = tid; i < EMB * NH; i += 288)
        sh_w1[i / NH][i % NH] = W1[NDEM * NH + i];

    // stage 16 embed rows (2048 floats)
    for (int i = tid; i < 16 * EMB; i += 288) {
        int kr = k0 + (i >> 7);
        sh_emb[i >> 7][i & 127] = (kr < VOCAB) ? embed[(long long)kr * EMB + (i & 127)] : 0.f;
    }
    __syncthreads();

    const int kl = tid / NP;
    const int n  = tid - kl * NP;
    const int k  = k0 + kl;

    float v = 0.f;
    if (k < VOCAB) {
        if (n < NH) {
            float a0 = 0.f, a1 = 0.f;
            #pragma unroll 16
            for (int d = 0; d < EMB; d += 2) {
                a0 += sh_emb[kl][d]     * sh_w1[d][n];
                a1 += sh_emb[kl][d + 1] * sh_w1[d + 1][n];
            }
            v = a0 + a1;
        } else if (n == NH) {
            v = 1.f;   // ones column -> counts
        }
    }
    g_EW1[k * NP + n] = v;
}

// ---------------------------------------------------------------------------
// Kernel 1: partial S[part] = mask_tile @ EW1_aug
//   Staging: batched float2 loads (MLP=8 per warp) -> 2 ballots per load.
//   Bit layout: word w = h*2+s (h = 64-col half, s = parity), col = 64h+s+2*bit.
// ---------------------------------------------------------------------------
__global__ __launch_bounds__(THREADS) void pool_kernel(const float* __restrict__ src) {
    __shared__ __align__(16) float sh_e[KT * NP];          // 9216 B
    __shared__ unsigned sh_bits[TM][KT / 32];              // 8192 B

    const int tid  = threadIdx.x;
    const int wid  = tid >> 5;
    const int lane = tid & 31;
    const int mtile = blockIdx.x >> 4;                     // / KSPLIT
    const int part  = blockIdx.x & (KSPLIT - 1);
    const int row0  = mtile * TM;
    const int kbase = part * KRANGE;
    const int r_loc = tid * 2;

    const float* sbase = src + (long long)row0 * SRC_COLS + NDEM;

    unsigned long long acc[2][9];
    #pragma unroll
    for (int r = 0; r < 2; ++r)
        #pragma unroll
        for (int j = 0; j < 9; ++j) acc[r][j] = 0ull;

    for (int t = 0; t < NTILES; ++t) {
        const int k0 = kbase + t * KT;

        // --- stage EW1 tile (KT x NP = 2304 floats, 9 per thread) ---
        #pragma unroll
        for (int i = 0; i < 9; ++i) {
            int idx = tid + i * THREADS;
            sh_e[idx] = g_EW1[k0 * NP + idx];
        }

        // --- stage src -> bitmask; 8 independent float2 loads, then ballots ---
        // item = row*2 + h covers TM rows x 2 halves of 64 cols each.
        for (int it0 = wid * 8; it0 < TM * 2; it0 += 8 * (THREADS / 32)) {
            float2 v[8];
            #pragma unroll
            for (int j = 0; j < 8; ++j) {
                int item = it0 + j;
                int row  = item >> 1;
                int h    = item & 1;
                int kg   = k0 + h * 64 + 2 * lane;
                float2 val = make_float2(0.f, 0.f);
                if (kg < VOCAB)
                    val = *reinterpret_cast<const float2*>(sbase + (long long)row * SRC_COLS + kg);
                v[j] = val;
            }
            #pragma unroll
            for (int j = 0; j < 8; ++j) {
                int item = it0 + j;
                int row  = item >> 1;
                int h    = item & 1;
                unsigned w0 = __ballot_sync(0xffffffffu, v[j].x != 0.f);
                unsigned w1 = __ballot_sync(0xffffffffu, v[j].y != 0.f);
                if (lane == 0) {
                    sh_bits[row][h * 2]     = w0;
                    sh_bits[row][h * 2 + 1] = w1;
                }
            }
        }
        __syncthreads();

        unsigned bw0[4], bw1[4];
        #pragma unroll
        for (int w = 0; w < 4; ++w) {
            bw0[w] = sh_bits[r_loc][w];
            bw1[w] = sh_bits[r_loc + 1][w];
        }

        #pragma unroll
        for (int w = 0; w < 4; ++w) {
            const unsigned b0 = bw0[w], b1 = bw1[w];
            const int cb = (w >> 1) * 64 + (w & 1);        // col = cb + 2*bit
            #pragma unroll 8
            for (int bit = 0; bit < 32; ++bit) {
                const float* ep = sh_e + (cb + 2 * bit) * NP;
                unsigned long long e[9];
                #pragma unroll
                for (int j = 0; j < 9; ++j)
                    e[j] = *reinterpret_cast<const unsigned long long*>(ep + 2 * j);
                float m0 = ((b0 >> bit) & 1u) ? 1.f : 0.f;
                float m1 = ((b1 >> bit) & 1u) ? 1.f : 0.f;
                unsigned long long m0p = pack2(m0, m0);
                unsigned long long m1p = pack2(m1, m1);
                #pragma unroll
                for (int j = 0; j < 9; ++j) {
                    fma_f32x2(acc[0][j], e[j], m0p);
                    fma_f32x2(acc[1][j], e[j], m1p);
                }
            }
        }
        __syncthreads();
    }

    // --- write partials column-major for coalesced reduction later ---
    #pragma unroll
    for (int r = 0; r < 2; ++r) {
        int rg = row0 + r_loc + r;
        #pragma unroll
        for (int j = 0; j < 9; ++j) {
            float lo, hi;
            unpack2(acc[r][j], lo, hi);
            g_S[(part * NP + 2 * j + 0) * B_ROWS + rg] = lo;
            g_S[(part * NP + 2 * j + 1) * B_ROWS + rg] = hi;
        }
    }
}

// ---------------------------------------------------------------------------
// Kernel 2: reduce K-split partials + MLP epilogue
// ---------------------------------------------------------------------------
__global__ void mlp_kernel(const float* __restrict__ src, const float* __restrict__ W1,
                           const float* __restrict__ b1, const float* __restrict__ W2,
                           const float* __restrict__ b2, float* __restrict__ out) {
    int r = blockIdx.x * blockDim.x + threadIdx.x;
    if (r >= B_ROWS) return;

    float s[17];
    #pragma unroll
    for (int n = 0; n < 17; ++n) s[n] = 0.f;
    #pragma unroll
    for (int p = 0; p < KSPLIT; ++p)
        #pragma unroll
        for (int n = 0; n < 17; ++n)
            s[n] += g_S[(p * NP + n) * B_ROWS + r];

    float inv = 1.f / s[16];
    float d0 = src[(long long)r * SRC_COLS + 0];
    float d1 = src[(long long)r * SRC_COLS + 1];

    float o0 = b2[0], o1 = b2[1];
    #pragma unroll
    for (int j = 0; j < NH; ++j) {
        float z = d0 * W1[j] + d1 * W1[NH + j] + s[j] * inv + b1[j];
        float h = tanhf(z);
        o0 += h * W2[2 * j + 0];
        o1 += h * W2[2 * j + 1];
    }
    out[2 * r + 0] = o0;
    out[2 * r + 1] = o1;
}

// ---------------------------------------------------------------------------
// Launch
// ---------------------------------------------------------------------------
extern "C" void kernel_launch(void* const* d_in, const int* in_sizes, int n_in,
                              void* d_out, int out_size) {
    int iSrc = 0, iEmb = 1, iW1 = 2, iB1 = 3, iW2 = 4, iB2 = 5;
    for (int i = 0; i < n_in; ++i) {
        int s = in_sizes[i];
        if      (s == B_ROWS * SRC_COLS)   iSrc = i;
        else if (s == VOCAB * EMB)         iEmb = i;
        else if (s == (NDEM + EMB) * NH)   iW1  = i;
        else if (s == NH)                  iB1  = i;
        else if (s == NH * 2)              iW2  = i;
        else if (s == 2)                   iB2  = i;
    }
    const float* src   = (const float*)d_in[iSrc];
    const float* embed = (const float*)d_in[iEmb];
    const float* W1    = (const float*)d_in[iW1];
    const float* b1    = (const float*)d_in[iB1];
    const float* W2    = (const float*)d_in[iW2];
    const float* b2    = (const float*)d_in[iB2];
    float* out = (float*)d_out;

    ew1_kernel<<<KPAD / 16, 288>>>(embed, W1);
    pool_kernel<<<MTILES * KSPLIT, THREADS>>>(src);
    mlp_kernel<<<(B_ROWS + 255) / 256, 256>>>(src, W1, b1, W2, b2, out);
}

// round 6
// speedup vs baseline: 2.6981x; 1.2998x over previous
#include <cuda_runtime.h>
#include <cstdint>
#include <cmath>

// ---------------------------------------------------------------------------
// Problem constants
// ---------------------------------------------------------------------------
#define VOCAB     10000
#define NDEM      2
#define EMB       128
#define B_ROWS    16384
#define SRC_COLS  10002
#define NH        16
#define KPAD      10240
#define KSPLIT    16
#define KRANGE    (KPAD / KSPLIT)    // 640
#define KT        64                 // k-columns per pipeline tile
#define NT        (KRANGE / KT)      // 10
#define TM        512                // rows per CTA
#define THREADS   256
#define NCTA      ((B_ROWS / TM) * KSPLIT)   // 512

// Scratch (__device__ globals: allocation-free rule)
__device__ float g_EW1[KPAD * NH];            // [vocab-col][16]
__device__ float g_S[KSPLIT * 17 * B_ROWS];   // 16 partials x (16 sums + count)

// ---------------------------------------------------------------------------
// packed f32x2 helpers
// ---------------------------------------------------------------------------
__device__ __forceinline__ void fma2(unsigned long long& d, unsigned long long a,
                                     unsigned long long b) {
    asm("fma.rn.f32x2 %0, %1, %2, %0;" : "+l"(d) : "l"(a), "l"(b));
}
__device__ __forceinline__ unsigned long long pack2(float lo, float hi) {
    unsigned long long r;
    asm("mov.b64 %0, {%1, %2};" : "=l"(r) : "r"(__float_as_uint(lo)), "r"(__float_as_uint(hi)));
    return r;
}
__device__ __forceinline__ void unpack2(unsigned long long v, float& lo, float& hi) {
    unsigned a, b;
    asm("mov.b64 {%0, %1}, %2;" : "=r"(a), "=r"(b) : "l"(v));
    lo = __uint_as_float(a); hi = __uint_as_float(b);
}
__device__ __forceinline__ void cp16(void* s, const void* g) {
    unsigned sa = (unsigned)__cvta_generic_to_shared(s);
    asm volatile("cp.async.cg.shared.global [%0], [%1], 16;" :: "r"(sa), "l"(g));
}

// ---------------------------------------------------------------------------
// Kernel 0: g_EW1[c][n] = sum_d embed[c][d] * W1[(2+d)*16+n]   (0 for c>=VOCAB)
// ---------------------------------------------------------------------------
__global__ __launch_bounds__(256) void ew1_kernel(const float* __restrict__ embed,
                                                  const float* __restrict__ W1) {
    __shared__ float sh_emb[16][EMB];
    __shared__ float sh_w1[EMB][NH];
    const int tid = threadIdx.x;
    const int c0  = blockIdx.x * 16;

    for (int i = tid; i < EMB * NH; i += 256)
        sh_w1[i >> 4][i & 15] = W1[NDEM * NH + i];
    for (int i = tid; i < 16 * EMB; i += 256) {
        int r = i >> 7, k = c0 + r;
        sh_emb[r][i & 127] = (k < VOCAB) ? embed[(long long)k * EMB + (i & 127)] : 0.f;
    }
    __syncthreads();

    const int r = tid >> 4, n = tid & 15, k = c0 + r;
    float a0 = 0.f, a1 = 0.f;
    #pragma unroll 16
    for (int d = 0; d < EMB; d += 2) {
        a0 += sh_emb[r][d]     * sh_w1[d][n];
        a1 += sh_emb[r][d + 1] * sh_w1[d + 1][n];
    }
    g_EW1[k * NH + n] = (k < VOCAB) ? (a0 + a1) : 0.f;
}

// ---------------------------------------------------------------------------
// Kernel 1: partial S = mask_tile @ EW1  (pipelined bitmask GEMM)
//   warp w owns rows [64w, 64w+64); thread tid handles rows 2tid, 2tid+1.
//   Bit layout (from float2 ballots): tile col k -> word (k&1), bit (k>>1).
// ---------------------------------------------------------------------------
__global__ __launch_bounds__(THREADS, 4) void pool_kernel(const float* __restrict__ src) {
    __shared__ __align__(16) float    sh_e[2][KT * NH];     // 2 x 4 KB
    __shared__ __align__(8)  unsigned sh_bits[2][TM][2];    // 2 x 4 KB

    const int tid  = threadIdx.x;
    const int w    = tid >> 5;
    const int lane = tid & 31;
    const int mtile = blockIdx.x >> 4;
    const int part  = blockIdx.x & (KSPLIT - 1);
    const int row0  = mtile * TM;
    const int kbase = part * KRANGE;
    const float* sb = src + (long long)row0 * SRC_COLS + NDEM;
    const int cl = 2 * lane;                     // lane's col offset in a tile (even)

    // ---------------- prologue: stage tile 0 ----------------
    cp16(&sh_e[0][tid * 4], g_EW1 + kbase * NH + tid * 4);
    asm volatile("cp.async.commit_group;");
    {
        const int c = kbase + cl;
        #pragma unroll 4
        for (int b = 0; b < 16; ++b) {
            float2 v[4];
            #pragma unroll
            for (int j = 0; j < 4; ++j) {
                int row = 64 * w + 4 * b + j;
                v[j] = (c < VOCAB)
                     ? __ldcs(reinterpret_cast<const float2*>(sb + (long long)row * SRC_COLS + c))
                     : make_float2(0.f, 0.f);
            }
            #pragma unroll
            for (int j = 0; j < 4; ++j) {
                unsigned w0 = __ballot_sync(0xffffffffu, v[j].x != 0.f);
                unsigned w1 = __ballot_sync(0xffffffffu, v[j].y != 0.f);
                if (lane == 0)
                    *reinterpret_cast<uint2*>(&sh_bits[0][64 * w + 4 * b + j][0]) = make_uint2(w0, w1);
            }
        }
    }
    asm volatile("cp.async.wait_group 0;" ::: "memory");
    __syncthreads();

    unsigned long long acc[2][8];
    #pragma unroll
    for (int r = 0; r < 2; ++r)
        #pragma unroll
        for (int i = 0; i < 8; ++i) acc[r][i] = 0ull;
    int cnt0 = 0, cnt1 = 0;

    // ---------------- main loop ----------------
    for (int t = 0; t < NT; ++t) {
        const int buf = t & 1, nbuf = buf ^ 1;
        const uint2 bw0 = *reinterpret_cast<const uint2*>(&sh_bits[buf][2 * tid][0]);
        const uint2 bw1 = *reinterpret_cast<const uint2*>(&sh_bits[buf][2 * tid + 1][0]);
        cnt0 += __popc(bw0.x) + __popc(bw0.y);
        cnt1 += __popc(bw1.x) + __popc(bw1.y);

        const bool stg = (t + 1 < NT);
        if (stg) {
            cp16(&sh_e[nbuf][tid * 4], g_EW1 + (kbase + (t + 1) * KT) * NH + tid * 4);
            asm volatile("cp.async.commit_group;");
        }
        const int cnx = kbase + (t + 1) * KT + cl;
        const unsigned sae = (unsigned)__cvta_generic_to_shared(&sh_e[buf][0]);

        #pragma unroll 4
        for (int b = 0; b < 16; ++b) {
            // 1) issue next-tile loads (independent of compute below)
            float2 v[4];
            if (stg) {
                #pragma unroll
                for (int j = 0; j < 4; ++j) {
                    int row = 64 * w + 4 * b + j;
                    v[j] = (cnx < VOCAB)
                         ? __ldcs(reinterpret_cast<const float2*>(sb + (long long)row * SRC_COLS + cnx))
                         : make_float2(0.f, 0.f);
                }
            }
            // 2) compute 4 k-columns of current tile
            //    col k -> ballot word (k & 1), bit (k >> 1)
            #pragma unroll
            for (int j = 0; j < 4; ++j) {
                const int k = 4 * b + j;
                const int bit = k >> 1;
                const unsigned wr0 = (k & 1) ? bw0.y : bw0.x;
                const unsigned wr1 = (k & 1) ? bw1.y : bw1.x;
                unsigned long long e[8];
                const unsigned sa = sae + k * 64;
                asm("ld.shared.v2.b64 {%0,%1}, [%2];"    : "=l"(e[0]), "=l"(e[1]) : "r"(sa));
                asm("ld.shared.v2.b64 {%0,%1}, [%2+16];" : "=l"(e[2]), "=l"(e[3]) : "r"(sa));
                asm("ld.shared.v2.b64 {%0,%1}, [%2+32];" : "=l"(e[4]), "=l"(e[5]) : "r"(sa));
                asm("ld.shared.v2.b64 {%0,%1}, [%2+48];" : "=l"(e[6]), "=l"(e[7]) : "r"(sa));
                const float m0f = ((wr0 >> bit) & 1u) ? 1.f : 0.f;
                const float m1f = ((wr1 >> bit) & 1u) ? 1.f : 0.f;
                const unsigned long long m0 = pack2(m0f, m0f);
                const unsigned long long m1 = pack2(m1f, m1f);
                #pragma unroll
                for (int i = 0; i < 8; ++i) {
                    fma2(acc[0][i], e[i], m0);
                    fma2(acc[1][i], e[i], m1);
                }
            }
            // 3) consume loads: ballots + STS into next-tile bits
            if (stg) {
                #pragma unroll
                for (int j = 0; j < 4; ++j) {
                    unsigned q0 = __ballot_sync(0xffffffffu, v[j].x != 0.f);
                    unsigned q1 = __ballot_sync(0xffffffffu, v[j].y != 0.f);
                    if (lane == 0)
                        *reinterpret_cast<uint2*>(&sh_bits[nbuf][64 * w + 4 * b + j][0]) = make_uint2(q0, q1);
                }
            }
        }
        if (stg) asm volatile("cp.async.wait_group 0;" ::: "memory");
        __syncthreads();
    }

    // ---------------- write partials (column-major) ----------------
    const int rg0 = row0 + 2 * tid, rg1 = rg0 + 1;
    #pragma unroll
    for (int i = 0; i < 8; ++i) {
        float lo, hi;
        unpack2(acc[0][i], lo, hi);
        g_S[(part * 17 + 2 * i + 0) * B_ROWS + rg0] = lo;
        g_S[(part * 17 + 2 * i + 1) * B_ROWS + rg0] = hi;
        unpack2(acc[1][i], lo, hi);
        g_S[(part * 17 + 2 * i + 0) * B_ROWS + rg1] = lo;
        g_S[(part * 17 + 2 * i + 1) * B_ROWS + rg1] = hi;
    }
    g_S[(part * 17 + 16) * B_ROWS + rg0] = (float)cnt0;
    g_S[(part * 17 + 16) * B_ROWS + rg1] = (float)cnt1;
}

// ---------------------------------------------------------------------------
// Kernel 2: reduce K-split partials + MLP epilogue
// ---------------------------------------------------------------------------
__global__ void mlp_kernel(const float* __restrict__ src, const float* __restrict__ W1,
                           const float* __restrict__ b1, const float* __restrict__ W2,
                           const float* __restrict__ b2, float* __restrict__ out) {
    int r = blockIdx.x * blockDim.x + threadIdx.x;
    if (r >= B_ROWS) return;

    float s[17];
    #pragma unroll
    for (int n = 0; n < 17; ++n) s[n] = 0.f;
    #pragma unroll
    for (int p = 0; p < KSPLIT; ++p)
        #pragma unroll
        for (int n = 0; n < 17; ++n)
            s[n] += g_S[(p * 17 + n) * B_ROWS + r];

    const float inv = 1.f / s[16];
    const float d0 = src[(long long)r * SRC_COLS + 0];
    const float d1 = src[(long long)r * SRC_COLS + 1];

    float o0 = b2[0], o1 = b2[1];
    #pragma unroll
    for (int j = 0; j < NH; ++j) {
        float z = d0 * W1[j] + d1 * W1[NH + j] + s[j] * inv + b1[j];
        float h = tanhf(z);
        o0 += h * W2[2 * j + 0];
        o1 += h * W2[2 * j + 1];
    }
    out[2 * r + 0] = o0;
    out[2 * r + 1] = o1;
}

// ---------------------------------------------------------------------------
// Launch
// ---------------------------------------------------------------------------
extern "C" void kernel_launch(void* const* d_in, const int* in_sizes, int n_in,
                              void* d_out, int out_size) {
    int iSrc = 0, iEmb = 1, iW1 = 2, iB1 = 3, iW2 = 4, iB2 = 5;
    for (int i = 0; i < n_in; ++i) {
        int s = in_sizes[i];
        if      (s == B_ROWS * SRC_COLS)  iSrc = i;
        else if (s == VOCAB * EMB)        iEmb = i;
        else if (s == (NDEM + EMB) * NH)  iW1  = i;
        else if (s == NH)                 iB1  = i;
        else if (s == NH * 2)             iW2  = i;
        else if (s == 2)                  iB2  = i;
    }
    const float* src   = (const float*)d_in[iSrc];
    const float* embed = (const float*)d_in[iEmb];
    const float* W1    = (const float*)d_in[iW1];
    const float* b1    = (const float*)d_in[iB1];
    const float* W2    = (const float*)d_in[iW2];
    const float* b2    = (const float*)d_in[iB2];
    float* out = (float*)d_out;

    ew1_kernel<<<KPAD / 16, 256>>>(embed, W1);
    pool_kernel<<<NCTA, THREADS>>>(src);
    mlp_kernel<<<(B_ROWS + 255) / 256, 256>>>(src, W1, b1, W2, b2, out);
}